// round 15
// baseline (speedup 1.0000x reference)
#include <cuda_runtime.h>
#include <cuda_bf16.h>

#define OUTSZ 224
#define NBINS 8
#define FW 512
#define FH 512
#define TPB 224                     // one thread per output column
#define SPLIT 16                    // CTAs per box
#define ROWS_PART (OUTSZ / SPLIT)   // 14 output rows per CTA
#define HALF 7                      // output rows per pass
#define NROWH 9                     // flow rows per pass: span <= 6.5px -> <= 9 rows
#define ZROW NROWH                  // extra zeroed row slot for masked rows
#define NBOX 512

// partial results: [box*SPLIT + part][bin]
__device__ float g_psum[NBOX * SPLIT * NBINS];
__device__ float g_pcnt[NBOX * SPLIT * NBINS];
__device__ unsigned int g_ticket[NBOX];   // zero-init; self-resetting each replay

__global__ __launch_bounds__(TPB, 8)
void vel_hist_kernel(const float* __restrict__ flows,
                     const float* __restrict__ boxes,
                     float* __restrict__ out)
{
    // s_lerp (both passes) aliased with count-staging buffers (post-loop)
    __shared__ __align__(16) char s_u[(NROWH + 1) * TPB * sizeof(float2)]; // 17920 B
    float2*       s_lerp = (float2*)s_u;
    unsigned int* s_c0   = (unsigned int*)s_u;
    unsigned int* s_c1   = ((unsigned int*)s_u) + TPB;

    __shared__ float4 s_row[HALF];        // {i0_bytes, i1_bytes, fy, -}
    __shared__ float  hsum[NBINS * TPB];  // stride 224: conflict-free
    __shared__ unsigned int s_flag;

    const int bx   = blockIdx.x;
    const int box  = bx >> 4;             // SPLIT = 16
    const int part = bx & 15;
    const int tid  = threadIdx.x;

    const float bf  = __ldg(boxes + box * 5 + 0);
    const float bx1 = __ldg(boxes + box * 5 + 1);
    const float by1 = __ldg(boxes + box * 5 + 2);
    const float bx2 = __ldg(boxes + box * 5 + 3);
    const float by2 = __ldg(boxes + box * 5 + 4);
    const int bidx = (int)bf;
    const float roi_w = fmaxf(bx2 - bx1, 1.0f);
    const float roi_h = fmaxf(by2 - by1, 1.0f);

    // ---- per-thread column params (no smem) ----
    float fx; int xa, xb; bool vx;
    {
        float g = ((float)tid + 0.5f) * (1.0f / OUTSZ);
        float px = bx1 + g * roi_w;
        vx = (px >= -1.0f && px <= (float)FW);
        float pcx = fminf(fmaxf(px, 0.0f), (float)(FW - 1));
        xa = (int)floorf(pcx);
        xb = min(xa + 1, FW - 1);
        fx = pcx - (float)xa;
    }

#pragma unroll
    for (int b = 0; b < NBINS; b++)
        hsum[b * TPB + tid] = 0.0f;
    s_lerp[ZROW * TPB + tid] = make_float2(0.0f, 0.0f);  // zero row (written once)

    const float* __restrict__ c0 = flows + (size_t)bidx * 2u * FH * FW;
    const float* __restrict__ c1 = c0 + FH * FW;
    const char* lb_base = (const char*)s_lerp + tid * sizeof(float2);
    float* msum = hsum + tid;
    unsigned int cnt0 = 0u, cnt1 = 0u;    // bins 0-3 / 4-7, 8-bit fields (max 14)

#pragma unroll
    for (int h = 0; h < 2; h++) {
        const int row0 = part * ROWS_PART + h * HALF;

        // flow-row range for this pass (identical computation in all threads)
        int ylo, yhi;
        {
            float g0 = ((float)row0 + 0.5f) * (1.0f / OUTSZ);
            float p0 = fminf(fmaxf(by1 + g0 * roi_h, 0.0f), (float)(FH - 1));
            ylo = (int)floorf(p0);
            float g1 = ((float)(row0 + HALF - 1) + 0.5f) * (1.0f / OUTSZ);
            float p1 = fminf(fmaxf(by1 + g1 * roi_h, 0.0f), (float)(FH - 1));
            yhi = min((int)floorf(p1) + 1, FH - 1);
            yhi = min(yhi, ylo + NROWH - 1);   // provable no-op; memory safety
        }

        __syncthreads();   // previous pass's s_lerp/s_row readers done (also covers init)

        if (tid < HALF) {  // y params: byte offsets into s_lerp (mask folded in)
            int row = row0 + tid;
            float g = ((float)row + 0.5f) * (1.0f / OUTSZ);
            float py = by1 + g * roi_h;
            bool vy = (py >= -1.0f && py <= (float)FH);
            float pcy = fminf(fmaxf(py, 0.0f), (float)(FH - 1));
            int yl = (int)floorf(pcy);
            int yh = min(yl + 1, FH - 1);
            float fy = pcy - (float)yl;
            int i0b = (yl - ylo) * (TPB * 8);
            int i1b = (yh - ylo) * (TPB * 8);
            if (!vy) { i0b = ZROW * (TPB * 8); i1b = i0b; }  // -> zero row => (+0,+0)
            s_row[tid] = make_float4(__int_as_float(i0b), __int_as_float(i1b), fy, 0.0f);
        }

        // ---- Phase 1: bulk load, all LDGs independent (MLP-bound) ----
#pragma unroll 3
        for (int y = ylo; y <= yhi; y++) {
            int o = y * FW;
            float la = __ldg(c0 + o + xa), lb = __ldg(c0 + o + xb);
            float lc = __ldg(c1 + o + xa), ld = __ldg(c1 + o + xb);
            float w0 = la + fx * (lb - la);
            float w1 = lc + fx * (ld - lc);
            if (!vx) { w0 = 0.0f; w1 = 0.0f; }  // masked column => exact (+0,+0)
            s_lerp[(y - ylo) * TPB + tid] = make_float2(w0, w1);
        }
        __syncthreads();

        // ---- Phase 2: branch-free compute, fully unrolled, lean ALU ----
#pragma unroll
        for (int r = 0; r < HALF; r++) {
            float4 rp = s_row[r];             // uniform LDS.128
            float2 v0 = *(const float2*)(lb_base + __float_as_int(rp.x));
            float2 v1 = *(const float2*)(lb_base + __float_as_int(rp.y));
            float fy = rp.z;

            float a = fmaf(fy, v1.x - v0.x, v0.x);
            float b = fmaf(fy, v1.y - v0.y, v0.y);

            float r2 = fmaf(a, a, b * b);
            float mag = r2 * rsqrtf(r2 + 1e-38f);  // r2=0 -> +0, no NaN

            // octant bin via LUT: idx = (a<0)<<2 | (b<0)<<1 | (|a|<=|b|)
            // (<= makes (+-0,+-0) -> bin 4 exactly; FSETP: -0 == +0)
            bool pa = a < 0.0f;
            bool pb = b < 0.0f;
            bool pc = fabsf(a) <= fabsf(b);
            int sh = (pa ? 16 : 0) + (pb ? 8 : 0) + (pc ? 4 : 0);
            unsigned int t = 0x01327645u >> sh;
            int bin = t & 7;

            msum[bin * TPB] += mag;
            unsigned int inc = 1u << ((t & 3) << 3);  // bin&3 == t&3
            if (pa) cnt0 += inc; else cnt1 += inc;    // a<0 <=> bin in 0..3
        }
    }

    __syncthreads();          // s_lerp reads done before aliasing as s_c
    s_c0[tid] = cnt0;
    s_c1[tid] = cnt1;
    __syncthreads();

    // 7 warps reduce 8 bins (warp w -> bins w, w+7)
    int wid = tid >> 5, lane = tid & 31;
    for (int bin = wid; bin < NBINS; bin += 7) {
        int shb = (bin & 3) << 3;
        const unsigned int* cc = (bin & 4) ? s_c1 : s_c0;
        float s = 0.0f;
        int   c = 0;
#pragma unroll
        for (int u = 0; u < TPB; u += 32) {
            s += hsum[bin * TPB + lane + u];
            c += (int)((cc[lane + u] >> shb) & 0xFFu);
        }
#pragma unroll
        for (int d = 16; d > 0; d >>= 1) {
            s += __shfl_down_sync(0xffffffffu, s, d);
            c += __shfl_down_sync(0xffffffffu, c, d);
        }
        if (lane == 0) {
            g_psum[bx * NBINS + bin] = s;
            g_pcnt[bx * NBINS + bin] = (float)c;
        }
    }

    // ---- fused finalize: last CTA per box combines partials ----
    // one release-atomic per CTA: ordering without __threadfence (no CCTL.IVALL)
    __syncthreads();
    if (tid == 0) {
        unsigned int old;
        asm volatile("atom.release.gpu.global.add.u32 %0, [%1], %2;"
                     : "=r"(old) : "l"(&g_ticket[box]), "r"(1u) : "memory");
        s_flag = (old == SPLIT - 1) ? 1u : 0u;
    }
    __syncthreads();
    if (s_flag) {
        if (tid < NBINS) {
            float s = 0.0f, c = 0.0f;
#pragma unroll
            for (int p = 0; p < SPLIT; p++) {   // __ldcg: L1-bypass, L2-coherent
                s += __ldcg(&g_psum[(box * SPLIT + p) * NBINS + tid]);
                c += __ldcg(&g_pcnt[(box * SPLIT + p) * NBINS + tid]);
            }
            out[box * NBINS + tid] = (c != 0.0f) ? (s / c) : 0.0f;
        }
        if (tid == 0) g_ticket[box] = 0u;   // reset for next graph replay
    }
}

extern "C" void kernel_launch(void* const* d_in, const int* in_sizes, int n_in,
                              void* d_out, int out_size) {
    const float* flows = (const float*)d_in[0];   // (8, 2, 512, 512) f32
    const float* boxes = (const float*)d_in[1];   // (512, 5) f32
    float* out = (float*)d_out;                   // (512, 8) f32
    vel_hist_kernel<<<NBOX * SPLIT, TPB>>>(flows, boxes, out);
}